// round 8
// baseline (speedup 1.0000x reference)
#include <cuda_runtime.h>

#define NN   2048
#define ORD  3
#define PTS  16
#define DIM1 64
#define DIM2 32
#define PL1  32
#define PL2  8
#define LBL  10
#define TGRID 256               // k_tail blocks; 8 rows each

// Scratch (no allocations allowed)
__device__ float    g_ms[NN * ORD * PTS];   // [n, 48]
__device__ float    g_num[PL2 * DIM2];
__device__ float    g_den[PL2];
__device__ unsigned g_cnt;

__device__ __forceinline__ float fast_tanh(float x) {
    float r;
    asm("tanh.approx.f32 %0, %1;" : "=f"(r) : "f"(x));
    return r;
}

// cos(2*pi*y): exact reduction + even poly through (2*pi*t)^14, max err ~4e-6
__device__ __forceinline__ float cos2pi(float y) {
    float t = y - rintf(y);
    float u = t * t;
    float p = -1.7143907f;
    p = fmaf(p, u,  7.9035539f);
    p = fmaf(p, u, -26.4257337f);
    p = fmaf(p, u,  60.2446418f);
    p = fmaf(p, u, -85.4567987f);
    p = fmaf(p, u,  64.9393940f);
    p = fmaf(p, u, -19.7392088f);
    p = fmaf(p, u,  1.0f);
    return p;
}

__device__ __forceinline__ int bitrev3(int x) {
    return ((x & 1) << 2) | (x & 2) | ((x & 4) >> 2);
}

// ---------------------------------------------------------------------------
// Kernel 1: pure MUFU kernel. One block per row; tail = reduce + 48-float STG.
// ---------------------------------------------------------------------------
__global__ __launch_bounds__(256, 6) void k_feats(const float* __restrict__ adj,
                                                  const float* __restrict__ wm) {
    const int i = blockIdx.x, tid = threadIdx.x;
    const int warp = tid >> 5, lane = tid & 31;

    __shared__ float s_w [ORD * PTS];
    __shared__ float s_ws[ORD * PTS];
    __shared__ float red[ORD][8][PTS];

    if (tid < ORD * PTS) {
        float w = wm[tid];
        s_w[tid]  = w;
        s_ws[tid] = w * 0.15915494309189535f;
    }
    __syncthreads();

    const float* base = adj + (size_t)i * NN;
#pragma unroll
    for (int o = 0; o < ORD; o++) {
        const float4* row = reinterpret_cast<const float4*>(base + (size_t)o * NN * NN);
        const float4 c0 = row[tid];
        const float4 c1 = row[tid + 256];
        const float xs[8] = {c0.x, c0.y, c0.z, c0.w, c1.x, c1.y, c1.z, c1.w};

#pragma unroll
        for (int s = 0; s < 2; s++) {
            float w[7], acc[8];
#pragma unroll
            for (int q = 0; q < 7; q++) { w[q] = s_w[o * PTS + s * 8 + q]; acc[q] = 0.f; }
            const float wsp = s_ws[o * PTS + s * 8 + 7];
            acc[7] = 0.f;

#pragma unroll
            for (int e = 0; e < 8; e++) {
                const float x = xs[e];
#pragma unroll
                for (int q = 0; q < 7; q++) acc[q] += __cosf(w[q] * x);
                acc[7] += cos2pi(wsp * x);
            }

            // split-butterfly: 8 accs -> 1 per lane (point = bitrev3(lane&7))
#pragma unroll
            for (int st = 0; st < 3; st++) {
                const int bit = 1 << st, half = 8 >> (st + 1);
                const bool hi = lane & bit;
#pragma unroll
                for (int q = 0; q < 4; q++) {
                    if (q < half) {
                        float send = hi ? acc[q] : acc[q + half];
                        float recv = __shfl_xor_sync(0xffffffffu, send, bit);
                        acc[q] = (hi ? acc[q + half] : acc[q]) + recv;
                    }
                }
            }
            float v = acc[0];
            v += __shfl_xor_sync(0xffffffffu, v, 8);
            v += __shfl_xor_sync(0xffffffffu, v, 16);
            if (lane < 8) red[o][warp][s * 8 + lane] = v;
        }
    }
    __syncthreads();

    if (tid < ORD * PTS) {
        const int o = tid >> 4, l = tid & 15;
        float s = 0.f;
#pragma unroll
        for (int wz = 0; wz < 8; wz++) s += red[o][wz][l];
        g_ms[(size_t)i * (ORD * PTS) + o * PTS + (l & 8) + bitrev3(l & 7)]
            = s * (1.0f / NN);
    }
}

// ---------------------------------------------------------------------------
// Kernel 2: MLP + pooling + head. 256 blocks x 256 thr; 8 rows per block,
// 4 rows in flight (64 threads each), pooling accumulated in registers,
// single atomicAdd per thread at the end; last block computes the head.
// ---------------------------------------------------------------------------
__global__ __launch_bounds__(256) void k_tail(
    const float* __restrict__ w1, const float* __restrict__ b1,
    const float* __restrict__ w2, const float* __restrict__ b2,
    const float* __restrict__ p1, const float* __restrict__ pb1,
    const float* __restrict__ p2, const float* __restrict__ pb2,
    const float* __restrict__ cw, const float* __restrict__ cb,
    float* __restrict__ out) {

    const int tid = threadIdx.x;
    const int lane = tid & 31, warp = tid >> 5;
    const int sub = tid >> 6, st = tid & 63;    // 4 subgroups of 64

    __shared__ float s_w1[48 * DIM1];
    __shared__ float s_w2[DIM1 * DIM2];
    __shared__ float s_p1[DIM2 * PL1];
    __shared__ float s_p2[PL1 * PL2];
    __shared__ float s_b1[DIM1], s_b2[DIM2], s_pb1[PL1], s_pb2[PL2];
    __shared__ float s_ms[4][48];
    __shared__ float s_h1[4][DIM1 + 1];
    __shared__ float s_h2[4][DIM2 + 1];
    __shared__ float s_ab[4][PL1 + 1];
    __shared__ float s_s[4][PL2];
    __shared__ unsigned s_last;

    for (int k = tid; k < 48 * DIM1;   k += 256) s_w1[k] = w1[k];
    for (int k = tid; k < DIM1 * DIM2; k += 256) s_w2[k] = w2[k];
    for (int k = tid; k < DIM2 * PL1;  k += 256) s_p1[k] = p1[k];
    for (int k = tid; k < PL1 * PL2;   k += 256) s_p2[k] = p2[k];
    if (tid < DIM1) s_b1[tid] = b1[tid];
    if (tid < DIM2) s_b2[tid] = b2[tid];
    if (tid < PL1)  s_pb1[tid] = pb1[tid];
    if (tid < PL2)  s_pb2[tid] = pb2[tid];
    __syncthreads();

    const int cc = tid >> 5, dd = tid & 31;     // pooling ownership (c,d)
    float num_acc = 0.f, den_acc = 0.f;

#pragma unroll
    for (int iter = 0; iter < 2; iter++) {
        const int r = blockIdx.x * 8 + iter * 4 + sub;

        if (st < 48) s_ms[sub][st] = g_ms[(size_t)r * 48 + st];
        __syncthreads();

        // h1: 64 outputs, one per thread
        {
            float a = s_b1[st];
#pragma unroll
            for (int k = 0; k < 48; k++) a = fmaf(s_ms[sub][k], s_w1[k * DIM1 + st], a);
            s_h1[sub][st] = fmaxf(a, 0.f);
        }
        __syncthreads();

        // h2: 32 outputs (st<32)
        if (st < DIM2) {
            float a = s_b2[st];
#pragma unroll
            for (int k = 0; k < DIM1; k++) a = fmaf(s_h1[sub][k], s_w2[k * DIM2 + st], a);
            s_h2[sub][st] = fmaxf(a, 0.f);
        }
        __syncthreads();

        // abstract: 32 outputs
        if (st < PL1) {
            float a = s_pb1[st];
#pragma unroll
            for (int k = 0; k < DIM2; k++) a = fmaf(s_h2[sub][k], s_p1[k * PL1 + st], a);
            s_ab[sub][st] = fast_tanh(a);
        }
        __syncthreads();

        // attention logits: 8 outputs
        if (st < PL2) {
            float a = s_pb2[st];
#pragma unroll
            for (int k = 0; k < PL1; k++) a = fmaf(s_ab[sub][k], s_p2[k * PL2 + st], a);
            s_s[sub][st] = a;
        }
        __syncthreads();

        // pooling: thread (cc,dd) accumulates over the 4 rows in flight
#pragma unroll
        for (int rr = 0; rr < 4; rr++) {
            float e = __expf(s_s[rr][cc]);      // |s| small: safe unshifted
            num_acc = fmaf(e, s_h2[rr][dd], num_acc);
            if (dd == 0) den_acc += e;
        }
        __syncthreads();
    }

    atomicAdd(&g_num[tid], num_acc);
    if (dd == 0) atomicAdd(&g_den[cc], den_acc);

    // ---- last block computes the head ----
    __threadfence();
    __syncthreads();
    if (tid == 0) s_last = (atomicAdd(&g_cnt, 1u) == TGRID - 1u) ? 1u : 0u;
    __syncthreads();
    if (!s_last) return;

    __shared__ float part[8][LBL];
    float v = __ldcg(&g_num[tid]) / __ldcg(&g_den[tid >> 5]);
    {
        float p[LBL];
#pragma unroll
        for (int l = 0; l < LBL; l++) p[l] = v * __ldg(cw + tid * LBL + l);
#pragma unroll
        for (int ofs = 16; ofs; ofs >>= 1)
#pragma unroll
            for (int l = 0; l < LBL; l++)
                p[l] += __shfl_xor_sync(0xffffffffu, p[l], ofs);
        if (lane == 0) {
#pragma unroll
            for (int l = 0; l < LBL; l++) part[warp][l] = p[l];
        }
    }
    __syncthreads();

    if (tid < 32) {
        float logit = -1e30f;
        if (tid < LBL) {
            float a = __ldg(cb + tid);
#pragma unroll
            for (int wz = 0; wz < 8; wz++) a += part[wz][tid];
            logit = a;
        }
        float m2 = logit;
#pragma unroll
        for (int ofs = 16; ofs; ofs >>= 1)
            m2 = fmaxf(m2, __shfl_xor_sync(0xffffffffu, m2, ofs));
        float ex = (tid < LBL) ? expf(logit - m2) : 0.f;
        float s2 = ex;
#pragma unroll
        for (int ofs = 16; ofs; ofs >>= 1)
            s2 += __shfl_xor_sync(0xffffffffu, s2, ofs);
        if (tid < LBL) out[tid] = logit - m2 - logf(s2);
    }
    __syncthreads();

    // reset for next graph replay
    __stcg(&g_num[tid], 0.f);
    if (tid < PL2) __stcg(&g_den[tid], 0.f);
    if (tid == 0) { __threadfence(); atomicExch(&g_cnt, 0u); }
}

// ---------------------------------------------------------------------------
extern "C" void kernel_launch(void* const* d_in, const int* in_sizes, int n_in,
                              void* d_out, int out_size) {
    const float* adj = (const float*)d_in[0];
    const float* wm  = (const float*)d_in[1];
    const float* w1  = (const float*)d_in[2];
    const float* b1  = (const float*)d_in[3];
    const float* w2  = (const float*)d_in[4];
    const float* b2  = (const float*)d_in[5];
    const float* p1  = (const float*)d_in[6];
    const float* pb1 = (const float*)d_in[7];
    const float* p2  = (const float*)d_in[8];
    const float* pb2 = (const float*)d_in[9];
    const float* cw  = (const float*)d_in[10];
    const float* cb  = (const float*)d_in[11];
    float* out = (float*)d_out;

    k_feats<<<NN, 256>>>(adj, wm);
    k_tail <<<TGRID, 256>>>(w1, b1, w2, b2, p1, pb1, p2, pb2, cw, cb, out);
}